// round 11
// baseline (speedup 1.0000x reference)
#include <cuda_runtime.h>
#include <cuda_fp16.h>
#include <mma.h>

using namespace nvcuda;

// SGC K=2:  out = Prop(Prop(x @ W)) + b   (projection commuted to the front)
// 5 kernels: gemm+deg fused, alloc (block-scan + atomic base + norm + scale),
// scatter, pull1, pull2.  Launch 4 == pull1 so ncu's capture shows it.

#define NN 100000
#define EE 3200000
#define IN_F 256
#define OUT_F 64
#define AB 1024
#define ANB ((NN + AB - 1) / AB)      // 98
#define CSR_CAP (EE + 3 * NN + 4)

// ---------------- scratch (static device globals; no allocation) -------------
__device__ float  g_y0f[NN * OUT_F];  // x@W, fp32 (unscaled)
__device__ __half g_y0h[NN * OUT_F];  // (x@W)*norm, fp16
__device__ __half g_z1h[NN * OUT_F];  // round-1 result * norm^2, fp16
__device__ float  g_norm[NN];
__device__ int    g_deg[NN];          // degree (memset 0 per call)
__device__ int    g_off[NN];          // CSR row offsets (padded to 4, unordered)
__device__ int    g_cur[NN];          // scatter cursors
__device__ int    g_csr[CSR_CAP];     // src ids grouped by dst
__device__ int    g_total;            // bump allocator (memset 0 per call)

// ---------------- kernel 1: y0f = x @ W (wmma)  +  degree histogram ----------
__global__ void __launch_bounds__(256) gemm_deg_kernel(const float* __restrict__ x,
                                                       const float* __restrict__ W,
                                                       const int* __restrict__ dst,
                                                       int N, int E) {
    __shared__ __half As[64][72];
    __shared__ __half Bs[64][72];
    __shared__ float  Os[64][68];

    const int t = threadIdx.x;
    const int w = t >> 5;
    const int wr = w >> 1;
    const int wc = w & 1;
    const int rowbase = blockIdx.x * 64;

    wmma::fragment<wmma::accumulator, 16, 16, 16, float> acc0, acc1;
    wmma::fill_fragment(acc0, 0.0f);
    wmma::fill_fragment(acc1, 0.0f);

    for (int kc = 0; kc < IN_F; kc += 64) {
        #pragma unroll
        for (int i = 0; i < 16; i++) {
            int lin = t + i * 256;
            int r = lin >> 6;
            int c = lin & 63;
            int gr = rowbase + r;
            float xv = (gr < N) ? x[(long long)gr * IN_F + kc + c] : 0.0f;
            As[r][c] = __float2half(xv);
            Bs[r][c] = __float2half(W[(kc + r) * OUT_F + c]);
        }
        __syncthreads();

        #pragma unroll
        for (int ks = 0; ks < 4; ks++) {
            wmma::fragment<wmma::matrix_a, 16, 16, 16, __half, wmma::row_major> af;
            wmma::load_matrix_sync(af, &As[wr * 16][ks * 16], 72);
            wmma::fragment<wmma::matrix_b, 16, 16, 16, __half, wmma::row_major> bf0, bf1;
            wmma::load_matrix_sync(bf0, &Bs[ks * 16][wc * 32], 72);
            wmma::load_matrix_sync(bf1, &Bs[ks * 16][wc * 32 + 16], 72);
            wmma::mma_sync(acc0, af, bf0, acc0);
            wmma::mma_sync(acc1, af, bf1, acc1);
        }
        __syncthreads();
    }

    wmma::store_matrix_sync(&Os[wr * 16][wc * 32], acc0, 68, wmma::mem_row_major);
    wmma::store_matrix_sync(&Os[wr * 16][wc * 32 + 16], acc1, 68, wmma::mem_row_major);
    __syncthreads();

    // epilogue: write unscaled fp32 (norm not known yet)
    {
        int r = t >> 2;
        int c0 = (t & 3) * 16;
        int gr = rowbase + r;
        if (gr < N) {
            float4* p = (float4*)&g_y0f[(long long)gr * OUT_F + c0];
            #pragma unroll
            for (int k = 0; k < 4; k++) {
                p[k] = make_float4(Os[r][c0 + 4 * k], Os[r][c0 + 4 * k + 1],
                                   Os[r][c0 + 4 * k + 2], Os[r][c0 + 4 * k + 3]);
            }
        }
    }

    // fused degree histogram: 8 edges per thread
    {
        int tg = blockIdx.x * 256 + t;
        int e = tg * 8;
        if (e + 8 <= E) {
            int4 d0 = __ldg((const int4*)(dst + e));
            int4 d1 = __ldg((const int4*)(dst + e + 4));
            atomicAdd(&g_deg[d0.x], 1);
            atomicAdd(&g_deg[d0.y], 1);
            atomicAdd(&g_deg[d0.z], 1);
            atomicAdd(&g_deg[d0.w], 1);
            atomicAdd(&g_deg[d1.x], 1);
            atomicAdd(&g_deg[d1.y], 1);
            atomicAdd(&g_deg[d1.z], 1);
            atomicAdd(&g_deg[d1.w], 1);
        } else if (e < E) {
            for (int k = e; k < E; k++) atomicAdd(&g_deg[dst[k]], 1);
        }
    }
}

// ---------------- kernel 2: alloc = block scan + atomic base + norm + scale --
// CSR bases need only be disjoint, not ordered: one atomicAdd per block.
__global__ void __launch_bounds__(AB) alloc_kernel(int N) {
    __shared__ int sh[AB];
    __shared__ int base_sh;
    int t = threadIdx.x;
    int i = blockIdx.x * AB + t;
    int dv = (i < N) ? g_deg[i] : 0;
    int vp = (dv + 3) & ~3;                 // pad rows to 4 for int4 loads
    sh[t] = vp;
    __syncthreads();
    for (int o = 1; o < AB; o <<= 1) {      // Hillis-Steele inclusive scan
        int a = (t >= o) ? sh[t - o] : 0;
        __syncthreads();
        sh[t] += a;
        __syncthreads();
    }
    if (t == AB - 1) base_sh = atomicAdd(&g_total, sh[AB - 1]);
    __syncthreads();
    if (i < N) {
        int excl = base_sh + sh[t] - vp;
        g_off[i] = excl;
        g_cur[i] = excl;
        float nm = rsqrtf(fmaxf((float)dv, 1.0f));
        g_norm[i] = nm;
        // y0h = fp16(y0f * norm)  (single rounding, same precision as before)
        const float2* sp = (const float2*)&g_y0f[(long long)i * OUT_F];
        __half2* dp = (__half2*)&g_y0h[(long long)i * OUT_F];
        #pragma unroll
        for (int k = 0; k < 32; k++) {
            float2 v = sp[k];
            dp[k] = __floats2half2_rn(v.x * nm, v.y * nm);
        }
    }
}

// ---------------- kernel 3: CSR fill, 4 edges/thread -------------------------
__global__ void scatter_kernel(const int* __restrict__ src,
                               const int* __restrict__ dst, int E) {
    int t = blockIdx.x * blockDim.x + threadIdx.x;
    int e = t * 4;
    if (e + 4 <= E) {
        int4 s = __ldg((const int4*)(src + e));
        int4 d = __ldg((const int4*)(dst + e));
        int p0 = atomicAdd(&g_cur[d.x], 1);
        int p1 = atomicAdd(&g_cur[d.y], 1);
        int p2 = atomicAdd(&g_cur[d.z], 1);
        int p3 = atomicAdd(&g_cur[d.w], 1);
        g_csr[p0] = s.x;
        g_csr[p1] = s.y;
        g_csr[p2] = s.z;
        g_csr[p3] = s.w;
    } else {
        for (int k = e; k < E; k++) {
            int pos = atomicAdd(&g_cur[dst[k]], 1);
            g_csr[pos] = src[k];
        }
    }
}

// ---------------- kernel 4: pull1  z1h[i] = fp16((sum y0h[s]) * norm[i]^2) ---
// one warp per node; int4 index loads (rows padded to 4)
__global__ void __launch_bounds__(256) pull1_kernel(int N) {
    int warp = (blockIdx.x * blockDim.x + threadIdx.x) >> 5;
    if (warp >= N) return;
    int lane = threadIdx.x & 31;
    int base = g_off[warp];
    int deg = g_deg[warp];
    const __half2* yp = (const __half2*)g_y0h;
    const int* cp = g_csr + base;

    float ax = 0.0f, ay = 0.0f;
    int j = 0;
    for (; j + 4 <= deg; j += 4) {
        int4 s = __ldg((const int4*)(cp + j));
        float2 v0 = __half22float2(__ldg(yp + s.x * 32 + lane));
        float2 v1 = __half22float2(__ldg(yp + s.y * 32 + lane));
        float2 v2 = __half22float2(__ldg(yp + s.z * 32 + lane));
        float2 v3 = __half22float2(__ldg(yp + s.w * 32 + lane));
        ax += v0.x + v1.x + v2.x + v3.x;
        ay += v0.y + v1.y + v2.y + v3.y;
    }
    if (j < deg) {
        int4 s = __ldg((const int4*)(cp + j));  // padded row: in-bounds
        {            float2 v = __half22float2(__ldg(yp + s.x * 32 + lane)); ax += v.x; ay += v.y; }
        if (j + 1 < deg) { float2 v = __half22float2(__ldg(yp + s.y * 32 + lane)); ax += v.x; ay += v.y; }
        if (j + 2 < deg) { float2 v = __half22float2(__ldg(yp + s.z * 32 + lane)); ax += v.x; ay += v.y; }
    }
    float nm = g_norm[warp];
    nm *= nm;
    ((__half2*)g_z1h)[warp * 32 + lane] = __floats2half2_rn(ax * nm, ay * nm);
}

// ---------------- kernel 5: pull2  out[i] = (sum z1h[s]) * norm[i] + b -------
__global__ void __launch_bounds__(256) pull2_kernel(const float* __restrict__ b,
                                                    float* __restrict__ out, int N) {
    int warp = (blockIdx.x * blockDim.x + threadIdx.x) >> 5;
    if (warp >= N) return;
    int lane = threadIdx.x & 31;
    int base = g_off[warp];
    int deg = g_deg[warp];
    const __half2* zp = (const __half2*)g_z1h;
    const int* cp = g_csr + base;

    float ax = 0.0f, ay = 0.0f;
    int j = 0;
    for (; j + 4 <= deg; j += 4) {
        int4 s = __ldg((const int4*)(cp + j));
        float2 v0 = __half22float2(__ldg(zp + s.x * 32 + lane));
        float2 v1 = __half22float2(__ldg(zp + s.y * 32 + lane));
        float2 v2 = __half22float2(__ldg(zp + s.z * 32 + lane));
        float2 v3 = __half22float2(__ldg(zp + s.w * 32 + lane));
        ax += v0.x + v1.x + v2.x + v3.x;
        ay += v0.y + v1.y + v2.y + v3.y;
    }
    if (j < deg) {
        int4 s = __ldg((const int4*)(cp + j));
        {            float2 v = __half22float2(__ldg(zp + s.x * 32 + lane)); ax += v.x; ay += v.y; }
        if (j + 1 < deg) { float2 v = __half22float2(__ldg(zp + s.y * 32 + lane)); ax += v.x; ay += v.y; }
        if (j + 2 < deg) { float2 v = __half22float2(__ldg(zp + s.z * 32 + lane)); ax += v.x; ay += v.y; }
    }
    float nm = g_norm[warp];
    float2 bb = __ldg((const float2*)b + lane);
    ((float2*)out)[warp * 32 + lane] =
        make_float2(ax * nm + bb.x, ay * nm + bb.y);
}

// ---------------- launch -----------------------------------------------------
extern "C" void kernel_launch(void* const* d_in, const int* in_sizes, int n_in,
                              void* d_out, int out_size) {
    const float* x   = (const float*)d_in[0];
    const int*   src = (const int*)d_in[1];
    const int*   dst = (const int*)d_in[2];
    const float* W   = (const float*)d_in[3];
    const float* b   = (const float*)d_in[4];
    float*       out = (float*)d_out;

    const int N = in_sizes[0] / IN_F;   // 100000
    const int E = in_sizes[1];          // 3200000

    void *p_deg, *p_total;
    cudaGetSymbolAddress(&p_deg, g_deg);
    cudaGetSymbolAddress(&p_total, g_total);
    cudaMemsetAsync(p_deg, 0, (size_t)N * sizeof(int));
    cudaMemsetAsync(p_total, 0, sizeof(int));

    // 1: GEMM (unscaled fp32 out) + fused degree histogram
    gemm_deg_kernel<<<(N + 63) / 64, 256>>>(x, W, dst, N, E);
    // 2: offsets (bump-allocated, padded), norm, scaled fp16 y0h
    alloc_kernel<<<ANB, AB>>>(N);
    // 3: CSR fill
    scatter_kernel<<<((E + 3) / 4 + 255) / 256, 256>>>(src, dst, E);
    // 4: pull round 1  (<- ncu capture slot)
    const int pb = 256;
    const int pgrid = (N * 32 + pb - 1) / pb;
    pull1_kernel<<<pgrid, pb>>>(N);
    // 5: pull round 2
    pull2_kernel<<<pgrid, pb>>>(b, out, N);
}

// round 12
// speedup vs baseline: 1.2458x; 1.2458x over previous
#include <cuda_runtime.h>
#include <cuda_fp16.h>
#include <mma.h>

using namespace nvcuda;

// SGC K=2:  out = Prop(Prop(x @ W)) + b   (projection commuted to the front)
// 5 kernels: deg, alloc(scan+norm), gemm(+fused scatter), pull1, pull2.
// Pulls use pairwise HADD2 reduction to halve the cvt/add instruction stream
// (pull1 measured issue-bound: 78.8% issue, alu 57.2%, L2 only 33%).

#define NN 100000
#define EE 3200000
#define IN_F 256
#define OUT_F 64
#define AB 1024
#define ANB ((NN + AB - 1) / AB)      // 98
#define CSR_CAP (EE + 3 * NN + 4)

// ---------------- scratch (static device globals; no allocation) -------------
__device__ __half g_y0h[NN * OUT_F];  // (x@W)*norm, fp16
__device__ __half g_z1h[NN * OUT_F];  // round-1 result * norm^2, fp16
__device__ float  g_norm[NN];
__device__ int    g_deg[NN];          // degree (memset 0 per call)
__device__ int    g_off[NN];          // CSR row offsets (padded to 4, unordered)
__device__ int    g_cur[NN];          // scatter cursors
__device__ int    g_csr[CSR_CAP];     // src ids grouped by dst
__device__ int    g_total;            // bump allocator (memset 0 per call)

// ---------------- kernel 1: degree histogram, 8 edges/thread -----------------
__global__ void deg_kernel(const int* __restrict__ dst, int E) {
    int t = blockIdx.x * blockDim.x + threadIdx.x;
    int e = t * 8;
    if (e + 8 <= E) {
        int4 d0 = __ldg((const int4*)(dst + e));
        int4 d1 = __ldg((const int4*)(dst + e + 4));
        atomicAdd(&g_deg[d0.x], 1);
        atomicAdd(&g_deg[d0.y], 1);
        atomicAdd(&g_deg[d0.z], 1);
        atomicAdd(&g_deg[d0.w], 1);
        atomicAdd(&g_deg[d1.x], 1);
        atomicAdd(&g_deg[d1.y], 1);
        atomicAdd(&g_deg[d1.z], 1);
        atomicAdd(&g_deg[d1.w], 1);
    } else if (e < E) {
        for (int k = e; k < E; k++) atomicAdd(&g_deg[dst[k]], 1);
    }
}

// ---------------- kernel 2: alloc = block scan + atomic base + norm ----------
// CSR bases need only be disjoint, not ordered: one atomicAdd per block.
__global__ void __launch_bounds__(AB) alloc_kernel(int N) {
    __shared__ int sh[AB];
    __shared__ int base_sh;
    int t = threadIdx.x;
    int i = blockIdx.x * AB + t;
    int dv = (i < N) ? g_deg[i] : 0;
    int vp = (dv + 3) & ~3;                 // pad rows to 4 for int4 loads
    sh[t] = vp;
    __syncthreads();
    for (int o = 1; o < AB; o <<= 1) {      // Hillis-Steele inclusive scan
        int a = (t >= o) ? sh[t - o] : 0;
        __syncthreads();
        sh[t] += a;
        __syncthreads();
    }
    if (t == AB - 1) base_sh = atomicAdd(&g_total, sh[AB - 1]);
    __syncthreads();
    if (i < N) {
        int excl = base_sh + sh[t] - vp;
        g_off[i] = excl;
        g_cur[i] = excl;
        g_norm[i] = rsqrtf(fmaxf((float)dv, 1.0f));
    }
}

// ---------------- kernel 3: y0h = fp16((x@W)*norm) via wmma + fused scatter --
__global__ void __launch_bounds__(256) gemm_scatter_kernel(
        const float* __restrict__ x, const float* __restrict__ W,
        const int* __restrict__ src, const int* __restrict__ dst,
        int N, int E) {
    __shared__ __half As[64][72];
    __shared__ __half Bs[64][72];
    __shared__ float  Os[64][68];

    const int t = threadIdx.x;
    const int w = t >> 5;
    const int wr = w >> 1;
    const int wc = w & 1;
    const int rowbase = blockIdx.x * 64;

    wmma::fragment<wmma::accumulator, 16, 16, 16, float> acc0, acc1;
    wmma::fill_fragment(acc0, 0.0f);
    wmma::fill_fragment(acc1, 0.0f);

    for (int kc = 0; kc < IN_F; kc += 64) {
        #pragma unroll
        for (int i = 0; i < 16; i++) {
            int lin = t + i * 256;
            int r = lin >> 6;
            int c = lin & 63;
            int gr = rowbase + r;
            float xv = (gr < N) ? x[(long long)gr * IN_F + kc + c] : 0.0f;
            As[r][c] = __float2half(xv);
            Bs[r][c] = __float2half(W[(kc + r) * OUT_F + c]);
        }
        __syncthreads();

        #pragma unroll
        for (int ks = 0; ks < 4; ks++) {
            wmma::fragment<wmma::matrix_a, 16, 16, 16, __half, wmma::row_major> af;
            wmma::load_matrix_sync(af, &As[wr * 16][ks * 16], 72);
            wmma::fragment<wmma::matrix_b, 16, 16, 16, __half, wmma::row_major> bf0, bf1;
            wmma::load_matrix_sync(bf0, &Bs[ks * 16][wc * 32], 72);
            wmma::load_matrix_sync(bf1, &Bs[ks * 16][wc * 32 + 16], 72);
            wmma::mma_sync(acc0, af, bf0, acc0);
            wmma::mma_sync(acc1, af, bf1, acc1);
        }
        __syncthreads();
    }

    wmma::store_matrix_sync(&Os[wr * 16][wc * 32], acc0, 68, wmma::mem_row_major);
    wmma::store_matrix_sync(&Os[wr * 16][wc * 32 + 16], acc1, 68, wmma::mem_row_major);
    __syncthreads();

    // epilogue: scale by norm, fp16, write (4 threads/row, 16 cols each)
    {
        int r = t >> 2;
        int c0 = (t & 3) * 16;
        int gr = rowbase + r;
        if (gr < N) {
            float nm = g_norm[gr];
            __half2* p = (__half2*)&g_y0h[(long long)gr * OUT_F + c0];
            #pragma unroll
            for (int k = 0; k < 8; k++) {
                p[k] = __floats2half2_rn(Os[r][c0 + 2 * k] * nm,
                                         Os[r][c0 + 2 * k + 1] * nm);
            }
        }
    }

    // fused CSR fill: 8 edges/thread (g_cur prepared by alloc_kernel)
    {
        int tg = blockIdx.x * 256 + t;
        int e = tg * 8;
        if (e + 8 <= E) {
            int4 s0 = __ldg((const int4*)(src + e));
            int4 s1 = __ldg((const int4*)(src + e + 4));
            int4 d0 = __ldg((const int4*)(dst + e));
            int4 d1 = __ldg((const int4*)(dst + e + 4));
            int p0 = atomicAdd(&g_cur[d0.x], 1);
            int p1 = atomicAdd(&g_cur[d0.y], 1);
            int p2 = atomicAdd(&g_cur[d0.z], 1);
            int p3 = atomicAdd(&g_cur[d0.w], 1);
            int p4 = atomicAdd(&g_cur[d1.x], 1);
            int p5 = atomicAdd(&g_cur[d1.y], 1);
            int p6 = atomicAdd(&g_cur[d1.z], 1);
            int p7 = atomicAdd(&g_cur[d1.w], 1);
            g_csr[p0] = s0.x;
            g_csr[p1] = s0.y;
            g_csr[p2] = s0.z;
            g_csr[p3] = s0.w;
            g_csr[p4] = s1.x;
            g_csr[p5] = s1.y;
            g_csr[p6] = s1.z;
            g_csr[p7] = s1.w;
        } else if (e < E) {
            for (int k = e; k < E; k++) {
                int pos = atomicAdd(&g_cur[dst[k]], 1);
                g_csr[pos] = src[k];
            }
        }
    }
}

// ---------------- kernel 4: pull1  z1h[i] = fp16((sum y0h[s]) * norm[i]^2) ---
// one warp per node; int4 index loads; PAIRWISE HADD2 then fp32 accumulate
__global__ void __launch_bounds__(256) pull1_kernel(int N) {
    int warp = (blockIdx.x * blockDim.x + threadIdx.x) >> 5;
    if (warp >= N) return;
    int lane = threadIdx.x & 31;
    int base = g_off[warp];
    int deg = g_deg[warp];
    const __half2* yp = (const __half2*)g_y0h;
    const int* cp = g_csr + base;

    float ax = 0.0f, ay = 0.0f;
    int j = 0;
    for (; j + 4 <= deg; j += 4) {
        int4 s = __ldg((const int4*)(cp + j));
        __half2 v0 = __ldg(yp + s.x * 32 + lane);
        __half2 v1 = __ldg(yp + s.y * 32 + lane);
        __half2 v2 = __ldg(yp + s.z * 32 + lane);
        __half2 v3 = __ldg(yp + s.w * 32 + lane);
        float2 f01 = __half22float2(__hadd2(v0, v1));
        float2 f23 = __half22float2(__hadd2(v2, v3));
        ax += f01.x + f23.x;
        ay += f01.y + f23.y;
    }
    if (j < deg) {
        int4 s = __ldg((const int4*)(cp + j));  // padded row: in-bounds
        {            float2 v = __half22float2(__ldg(yp + s.x * 32 + lane)); ax += v.x; ay += v.y; }
        if (j + 1 < deg) { float2 v = __half22float2(__ldg(yp + s.y * 32 + lane)); ax += v.x; ay += v.y; }
        if (j + 2 < deg) { float2 v = __half22float2(__ldg(yp + s.z * 32 + lane)); ax += v.x; ay += v.y; }
    }
    float nm = g_norm[warp];
    nm *= nm;
    ((__half2*)g_z1h)[warp * 32 + lane] = __floats2half2_rn(ax * nm, ay * nm);
}

// ---------------- kernel 5: pull2  out[i] = (sum z1h[s]) * norm[i] + b -------
__global__ void __launch_bounds__(256) pull2_kernel(const float* __restrict__ b,
                                                    float* __restrict__ out, int N) {
    int warp = (blockIdx.x * blockDim.x + threadIdx.x) >> 5;
    if (warp >= N) return;
    int lane = threadIdx.x & 31;
    int base = g_off[warp];
    int deg = g_deg[warp];
    const __half2* zp = (const __half2*)g_z1h;
    const int* cp = g_csr + base;

    float ax = 0.0f, ay = 0.0f;
    int j = 0;
    for (; j + 4 <= deg; j += 4) {
        int4 s = __ldg((const int4*)(cp + j));
        __half2 v0 = __ldg(zp + s.x * 32 + lane);
        __half2 v1 = __ldg(zp + s.y * 32 + lane);
        __half2 v2 = __ldg(zp + s.z * 32 + lane);
        __half2 v3 = __ldg(zp + s.w * 32 + lane);
        float2 f01 = __half22float2(__hadd2(v0, v1));
        float2 f23 = __half22float2(__hadd2(v2, v3));
        ax += f01.x + f23.x;
        ay += f01.y + f23.y;
    }
    if (j < deg) {
        int4 s = __ldg((const int4*)(cp + j));
        {            float2 v = __half22float2(__ldg(zp + s.x * 32 + lane)); ax += v.x; ay += v.y; }
        if (j + 1 < deg) { float2 v = __half22float2(__ldg(zp + s.y * 32 + lane)); ax += v.x; ay += v.y; }
        if (j + 2 < deg) { float2 v = __half22float2(__ldg(zp + s.z * 32 + lane)); ax += v.x; ay += v.y; }
    }
    float nm = g_norm[warp];
    float2 bb = __ldg((const float2*)b + lane);
    ((float2*)out)[warp * 32 + lane] =
        make_float2(ax * nm + bb.x, ay * nm + bb.y);
}

// ---------------- launch -----------------------------------------------------
extern "C" void kernel_launch(void* const* d_in, const int* in_sizes, int n_in,
                              void* d_out, int out_size) {
    const float* x   = (const float*)d_in[0];
    const int*   src = (const int*)d_in[1];
    const int*   dst = (const int*)d_in[2];
    const float* W   = (const float*)d_in[3];
    const float* b   = (const float*)d_in[4];
    float*       out = (float*)d_out;

    const int N = in_sizes[0] / IN_F;   // 100000
    const int E = in_sizes[1];          // 3200000

    void *p_deg, *p_total;
    cudaGetSymbolAddress(&p_deg, g_deg);
    cudaGetSymbolAddress(&p_total, g_total);
    cudaMemsetAsync(p_deg, 0, (size_t)N * sizeof(int));
    cudaMemsetAsync(p_total, 0, sizeof(int));

    // 1: degree histogram
    const int et = (E + 7) / 8;
    deg_kernel<<<(et + 255) / 256, 256>>>(dst, E);
    // 2: offsets (bump-allocated, padded) + norm
    alloc_kernel<<<ANB, AB>>>(N);
    // 3: GEMM (scaled fp16 out) + fused CSR fill
    gemm_scatter_kernel<<<(N + 63) / 64, 256>>>(x, W, src, dst, N, E);
    // 4: pull round 1  (<- ncu capture slot)
    const int pb = 256;
    const int pgrid = (N * 32 + pb - 1) / pb;
    pull1_kernel<<<pgrid, pb>>>(N);
    // 5: pull round 2
    pull2_kernel<<<pgrid, pb>>>(b, out, N);
}

// round 13
// speedup vs baseline: 1.2793x; 1.0269x over previous
#include <cuda_runtime.h>
#include <cuda_fp16.h>
#include <mma.h>

using namespace nvcuda;

// SGC K=2:  out = Prop(Prop(x @ W)) + b   (projection commuted to the front)
// 5 kernels: deg, alloc(scan+norm), gemm(+fused scatter), pull1, pull2.
// Pulls: issue-bound (75% issue, alu 55%) -> attack instructions/edge:
//   - CSR stores PREMULTIPLIED byte offsets (src*128) -> IADD-only addressing
//   - 8-wide unroll halves loop-carried overhead
//   - pairwise HADD2 then fp32 accumulate (same precision as R12)

#define NN 100000
#define EE 3200000
#define IN_F 256
#define OUT_F 64
#define AB 1024
#define ANB ((NN + AB - 1) / AB)      // 98
#define CSR_CAP (EE + 3 * NN + 4)

// ---------------- scratch (static device globals; no allocation) -------------
__device__ __half g_y0h[NN * OUT_F];  // (x@W)*norm, fp16
__device__ __half g_z1h[NN * OUT_F];  // round-1 result * norm^2, fp16
__device__ float  g_norm[NN];
__device__ int    g_deg[NN];          // degree (memset 0 per call)
__device__ int    g_off[NN];          // CSR row offsets (padded to 4, unordered)
__device__ int    g_cur[NN];          // scatter cursors
__device__ int    g_csr[CSR_CAP];     // BYTE offsets (src*128) grouped by dst
__device__ int    g_total;            // bump allocator (memset 0 per call)

// ---------------- kernel 1: degree histogram, 8 edges/thread -----------------
__global__ void deg_kernel(const int* __restrict__ dst, int E) {
    int t = blockIdx.x * blockDim.x + threadIdx.x;
    int e = t * 8;
    if (e + 8 <= E) {
        int4 d0 = __ldg((const int4*)(dst + e));
        int4 d1 = __ldg((const int4*)(dst + e + 4));
        atomicAdd(&g_deg[d0.x], 1);
        atomicAdd(&g_deg[d0.y], 1);
        atomicAdd(&g_deg[d0.z], 1);
        atomicAdd(&g_deg[d0.w], 1);
        atomicAdd(&g_deg[d1.x], 1);
        atomicAdd(&g_deg[d1.y], 1);
        atomicAdd(&g_deg[d1.z], 1);
        atomicAdd(&g_deg[d1.w], 1);
    } else if (e < E) {
        for (int k = e; k < E; k++) atomicAdd(&g_deg[dst[k]], 1);
    }
}

// ---------------- kernel 2: alloc = block scan + atomic base + norm ----------
__global__ void __launch_bounds__(AB) alloc_kernel(int N) {
    __shared__ int sh[AB];
    __shared__ int base_sh;
    int t = threadIdx.x;
    int i = blockIdx.x * AB + t;
    int dv = (i < N) ? g_deg[i] : 0;
    int vp = (dv + 3) & ~3;                 // pad rows to 4 for int4 loads
    sh[t] = vp;
    __syncthreads();
    for (int o = 1; o < AB; o <<= 1) {      // Hillis-Steele inclusive scan
        int a = (t >= o) ? sh[t - o] : 0;
        __syncthreads();
        sh[t] += a;
        __syncthreads();
    }
    if (t == AB - 1) base_sh = atomicAdd(&g_total, sh[AB - 1]);
    __syncthreads();
    if (i < N) {
        int excl = base_sh + sh[t] - vp;
        g_off[i] = excl;
        g_cur[i] = excl;
        g_norm[i] = rsqrtf(fmaxf((float)dv, 1.0f));
    }
}

// ---------------- kernel 3: y0h = fp16((x@W)*norm) via wmma + fused scatter --
__global__ void __launch_bounds__(256) gemm_scatter_kernel(
        const float* __restrict__ x, const float* __restrict__ W,
        const int* __restrict__ src, const int* __restrict__ dst,
        int N, int E) {
    __shared__ __half As[64][72];
    __shared__ __half Bs[64][72];
    __shared__ float  Os[64][68];

    const int t = threadIdx.x;
    const int w = t >> 5;
    const int wr = w >> 1;
    const int wc = w & 1;
    const int rowbase = blockIdx.x * 64;

    wmma::fragment<wmma::accumulator, 16, 16, 16, float> acc0, acc1;
    wmma::fill_fragment(acc0, 0.0f);
    wmma::fill_fragment(acc1, 0.0f);

    for (int kc = 0; kc < IN_F; kc += 64) {
        #pragma unroll
        for (int i = 0; i < 16; i++) {
            int lin = t + i * 256;
            int r = lin >> 6;
            int c = lin & 63;
            int gr = rowbase + r;
            float xv = (gr < N) ? x[(long long)gr * IN_F + kc + c] : 0.0f;
            As[r][c] = __float2half(xv);
            Bs[r][c] = __float2half(W[(kc + r) * OUT_F + c]);
        }
        __syncthreads();

        #pragma unroll
        for (int ks = 0; ks < 4; ks++) {
            wmma::fragment<wmma::matrix_a, 16, 16, 16, __half, wmma::row_major> af;
            wmma::load_matrix_sync(af, &As[wr * 16][ks * 16], 72);
            wmma::fragment<wmma::matrix_b, 16, 16, 16, __half, wmma::row_major> bf0, bf1;
            wmma::load_matrix_sync(bf0, &Bs[ks * 16][wc * 32], 72);
            wmma::load_matrix_sync(bf1, &Bs[ks * 16][wc * 32 + 16], 72);
            wmma::mma_sync(acc0, af, bf0, acc0);
            wmma::mma_sync(acc1, af, bf1, acc1);
        }
        __syncthreads();
    }

    wmma::store_matrix_sync(&Os[wr * 16][wc * 32], acc0, 68, wmma::mem_row_major);
    wmma::store_matrix_sync(&Os[wr * 16][wc * 32 + 16], acc1, 68, wmma::mem_row_major);
    __syncthreads();

    // epilogue: scale by norm, fp16, write (4 threads/row, 16 cols each)
    {
        int r = t >> 2;
        int c0 = (t & 3) * 16;
        int gr = rowbase + r;
        if (gr < N) {
            float nm = g_norm[gr];
            __half2* p = (__half2*)&g_y0h[(long long)gr * OUT_F + c0];
            #pragma unroll
            for (int k = 0; k < 8; k++) {
                p[k] = __floats2half2_rn(Os[r][c0 + 2 * k] * nm,
                                         Os[r][c0 + 2 * k + 1] * nm);
            }
        }
    }

    // fused CSR fill: 8 edges/thread; store PREMULTIPLIED byte offsets (s*128)
    {
        int tg = blockIdx.x * 256 + t;
        int e = tg * 8;
        if (e + 8 <= E) {
            int4 s0 = __ldg((const int4*)(src + e));
            int4 s1 = __ldg((const int4*)(src + e + 4));
            int4 d0 = __ldg((const int4*)(dst + e));
            int4 d1 = __ldg((const int4*)(dst + e + 4));
            int p0 = atomicAdd(&g_cur[d0.x], 1);
            int p1 = atomicAdd(&g_cur[d0.y], 1);
            int p2 = atomicAdd(&g_cur[d0.z], 1);
            int p3 = atomicAdd(&g_cur[d0.w], 1);
            int p4 = atomicAdd(&g_cur[d1.x], 1);
            int p5 = atomicAdd(&g_cur[d1.y], 1);
            int p6 = atomicAdd(&g_cur[d1.z], 1);
            int p7 = atomicAdd(&g_cur[d1.w], 1);
            g_csr[p0] = s0.x << 7;
            g_csr[p1] = s0.y << 7;
            g_csr[p2] = s0.z << 7;
            g_csr[p3] = s0.w << 7;
            g_csr[p4] = s1.x << 7;
            g_csr[p5] = s1.y << 7;
            g_csr[p6] = s1.z << 7;
            g_csr[p7] = s1.w << 7;
        } else if (e < E) {
            for (int k = e; k < E; k++) {
                int pos = atomicAdd(&g_cur[dst[k]], 1);
                g_csr[pos] = src[k] << 7;
            }
        }
    }
}

// ---------------- pull helper: load half2 at byte offset ---------------------
__device__ __forceinline__ __half2 ldh2(const char* base, int soff) {
    return __ldg((const __half2*)(base + soff));
}

// ---------------- kernel 4: pull1  z1h[i] = fp16((sum y0h[s]) * norm[i]^2) ---
// one warp per node; int4 byte-offset loads; 8-wide unroll; pairwise HADD2
__global__ void __launch_bounds__(256) pull1_kernel(int N) {
    int warp = (blockIdx.x * blockDim.x + threadIdx.x) >> 5;
    if (warp >= N) return;
    int lane = threadIdx.x & 31;
    int base = g_off[warp];
    int deg = g_deg[warp];
    const char* yb = (const char*)g_y0h + lane * 4;   // lane folded into base
    const int* cp = g_csr + base;

    float ax = 0.0f, ay = 0.0f;
    int j = 0;
    for (; j + 8 <= deg; j += 8) {
        int4 sA = __ldg((const int4*)(cp + j));
        int4 sB = __ldg((const int4*)(cp + j + 4));
        __half2 v0 = ldh2(yb, sA.x);
        __half2 v1 = ldh2(yb, sA.y);
        __half2 v2 = ldh2(yb, sA.z);
        __half2 v3 = ldh2(yb, sA.w);
        __half2 v4 = ldh2(yb, sB.x);
        __half2 v5 = ldh2(yb, sB.y);
        __half2 v6 = ldh2(yb, sB.z);
        __half2 v7 = ldh2(yb, sB.w);
        float2 f01 = __half22float2(__hadd2(v0, v1));
        float2 f23 = __half22float2(__hadd2(v2, v3));
        float2 f45 = __half22float2(__hadd2(v4, v5));
        float2 f67 = __half22float2(__hadd2(v6, v7));
        ax += (f01.x + f23.x) + (f45.x + f67.x);
        ay += (f01.y + f23.y) + (f45.y + f67.y);
    }
    for (; j + 4 <= deg; j += 4) {
        int4 s = __ldg((const int4*)(cp + j));
        __half2 v0 = ldh2(yb, s.x);
        __half2 v1 = ldh2(yb, s.y);
        __half2 v2 = ldh2(yb, s.z);
        __half2 v3 = ldh2(yb, s.w);
        float2 f01 = __half22float2(__hadd2(v0, v1));
        float2 f23 = __half22float2(__hadd2(v2, v3));
        ax += f01.x + f23.x;
        ay += f01.y + f23.y;
    }
    if (j < deg) {
        int4 s = __ldg((const int4*)(cp + j));  // padded row: in-bounds
        {            float2 v = __half22float2(ldh2(yb, s.x)); ax += v.x; ay += v.y; }
        if (j + 1 < deg) { float2 v = __half22float2(ldh2(yb, s.y)); ax += v.x; ay += v.y; }
        if (j + 2 < deg) { float2 v = __half22float2(ldh2(yb, s.z)); ax += v.x; ay += v.y; }
    }
    float nm = g_norm[warp];
    nm *= nm;
    ((__half2*)g_z1h)[warp * 32 + lane] = __floats2half2_rn(ax * nm, ay * nm);
}

// ---------------- kernel 5: pull2  out[i] = (sum z1h[s]) * norm[i] + b -------
__global__ void __launch_bounds__(256) pull2_kernel(const float* __restrict__ b,
                                                    float* __restrict__ out, int N) {
    int warp = (blockIdx.x * blockDim.x + threadIdx.x) >> 5;
    if (warp >= N) return;
    int lane = threadIdx.x & 31;
    int base = g_off[warp];
    int deg = g_deg[warp];
    const char* zb = (const char*)g_z1h + lane * 4;
    const int* cp = g_csr + base;

    float ax = 0.0f, ay = 0.0f;
    int j = 0;
    for (; j + 8 <= deg; j += 8) {
        int4 sA = __ldg((const int4*)(cp + j));
        int4 sB = __ldg((const int4*)(cp + j + 4));
        __half2 v0 = ldh2(zb, sA.x);
        __half2 v1 = ldh2(zb, sA.y);
        __half2 v2 = ldh2(zb, sA.z);
        __half2 v3 = ldh2(zb, sA.w);
        __half2 v4 = ldh2(zb, sB.x);
        __half2 v5 = ldh2(zb, sB.y);
        __half2 v6 = ldh2(zb, sB.z);
        __half2 v7 = ldh2(zb, sB.w);
        float2 f01 = __half22float2(__hadd2(v0, v1));
        float2 f23 = __half22float2(__hadd2(v2, v3));
        float2 f45 = __half22float2(__hadd2(v4, v5));
        float2 f67 = __half22float2(__hadd2(v6, v7));
        ax += (f01.x + f23.x) + (f45.x + f67.x);
        ay += (f01.y + f23.y) + (f45.y + f67.y);
    }
    for (; j + 4 <= deg; j += 4) {
        int4 s = __ldg((const int4*)(cp + j));
        __half2 v0 = ldh2(zb, s.x);
        __half2 v1 = ldh2(zb, s.y);
        __half2 v2 = ldh2(zb, s.z);
        __half2 v3 = ldh2(zb, s.w);
        float2 f01 = __half22float2(__hadd2(v0, v1));
        float2 f23 = __half22float2(__hadd2(v2, v3));
        ax += f01.x + f23.x;
        ay += f01.y + f23.y;
    }
    if (j < deg) {
        int4 s = __ldg((const int4*)(cp + j));
        {            float2 v = __half22float2(ldh2(zb, s.x)); ax += v.x; ay += v.y; }
        if (j + 1 < deg) { float2 v = __half22float2(ldh2(zb, s.y)); ax += v.x; ay += v.y; }
        if (j + 2 < deg) { float2 v = __half22float2(ldh2(zb, s.z)); ax += v.x; ay += v.y; }
    }
    float nm = g_norm[warp];
    float2 bb = __ldg((const float2*)b + lane);
    ((float2*)out)[warp * 32 + lane] =
        make_float2(ax * nm + bb.x, ay * nm + bb.y);
}

// ---------------- launch -----------------------------------------------------
extern "C" void kernel_launch(void* const* d_in, const int* in_sizes, int n_in,
                              void* d_out, int out_size) {
    const float* x   = (const float*)d_in[0];
    const int*   src = (const int*)d_in[1];
    const int*   dst = (const int*)d_in[2];
    const float* W   = (const float*)d_in[3];
    const float* b   = (const float*)d_in[4];
    float*       out = (float*)d_out;

    const int N = in_sizes[0] / IN_F;   // 100000
    const int E = in_sizes[1];          // 3200000

    void *p_deg, *p_total;
    cudaGetSymbolAddress(&p_deg, g_deg);
    cudaGetSymbolAddress(&p_total, g_total);
    cudaMemsetAsync(p_deg, 0, (size_t)N * sizeof(int));
    cudaMemsetAsync(p_total, 0, sizeof(int));

    // 1: degree histogram
    const int et = (E + 7) / 8;
    deg_kernel<<<(et + 255) / 256, 256>>>(dst, E);
    // 2: offsets (bump-allocated, padded) + norm
    alloc_kernel<<<ANB, AB>>>(N);
    // 3: GEMM (scaled fp16 out) + fused CSR fill (byte offsets)
    gemm_scatter_kernel<<<(N + 63) / 64, 256>>>(x, W, src, dst, N, E);
    // 4: pull round 1  (<- ncu capture slot)
    const int pb = 256;
    const int pgrid = (N * 32 + pb - 1) / pb;
    pull1_kernel<<<pgrid, pb>>>(N);
    // 5: pull round 2
    pull2_kernel<<<pgrid, pb>>>(b, out, N);
}

// round 14
// speedup vs baseline: 1.4947x; 1.1684x over previous
#include <cuda_runtime.h>
#include <cuda_fp16.h>
#include <mma.h>

using namespace nvcuda;

// SGC K=2:  out = Prop(Prop(x @ W)) + b   (projection commuted to the front)
// 6 launches: deg, alloc, NOP, gemm(+scatter) <- ncu slot 4, pull1, pull2.
// - gemm smem load path vectorized (float4 -> 2x half2, 8B STS)
// - pulls: depth-2 HADD2 tree then fp32 accumulate

#define NN 100000
#define EE 3200000
#define IN_F 256
#define OUT_F 64
#define AB 1024
#define ANB ((NN + AB - 1) / AB)      // 98
#define CSR_CAP (EE + 3 * NN + 4)

// ---------------- scratch (static device globals; no allocation) -------------
__device__ __half g_y0h[NN * OUT_F];  // (x@W)*norm, fp16
__device__ __half g_z1h[NN * OUT_F];  // round-1 result * norm^2, fp16
__device__ float  g_norm[NN];
__device__ int    g_deg[NN];          // degree (memset 0 per call)
__device__ int    g_off[NN];          // CSR row offsets (padded to 4, unordered)
__device__ int    g_cur[NN];          // scatter cursors
__device__ int    g_csr[CSR_CAP];     // BYTE offsets (src*128) grouped by dst
__device__ int    g_total;            // bump allocator (memset 0 per call)

// ---------------- kernel 1: degree histogram, 8 edges/thread -----------------
__global__ void deg_kernel(const int* __restrict__ dst, int E) {
    int t = blockIdx.x * blockDim.x + threadIdx.x;
    int e = t * 8;
    if (e + 8 <= E) {
        int4 d0 = __ldg((const int4*)(dst + e));
        int4 d1 = __ldg((const int4*)(dst + e + 4));
        atomicAdd(&g_deg[d0.x], 1);
        atomicAdd(&g_deg[d0.y], 1);
        atomicAdd(&g_deg[d0.z], 1);
        atomicAdd(&g_deg[d0.w], 1);
        atomicAdd(&g_deg[d1.x], 1);
        atomicAdd(&g_deg[d1.y], 1);
        atomicAdd(&g_deg[d1.z], 1);
        atomicAdd(&g_deg[d1.w], 1);
    } else if (e < E) {
        for (int k = e; k < E; k++) atomicAdd(&g_deg[dst[k]], 1);
    }
}

// ---------------- kernel 2: alloc = block scan + atomic base + norm ----------
__global__ void __launch_bounds__(AB) alloc_kernel(int N) {
    __shared__ int sh[AB];
    __shared__ int base_sh;
    int t = threadIdx.x;
    int i = blockIdx.x * AB + t;
    int dv = (i < N) ? g_deg[i] : 0;
    int vp = (dv + 3) & ~3;                 // pad rows to 4 for int4 loads
    sh[t] = vp;
    __syncthreads();
    for (int o = 1; o < AB; o <<= 1) {      // Hillis-Steele inclusive scan
        int a = (t >= o) ? sh[t - o] : 0;
        __syncthreads();
        sh[t] += a;
        __syncthreads();
    }
    if (t == AB - 1) base_sh = atomicAdd(&g_total, sh[AB - 1]);
    __syncthreads();
    if (i < N) {
        int excl = base_sh + sh[t] - vp;
        g_off[i] = excl;
        g_cur[i] = excl;
        g_norm[i] = rsqrtf(fmaxf((float)dv, 1.0f));
    }
}

// ---------------- kernel 3: NOP (slot filler so slot 4 = gemm_scatter) -------
__global__ void nop_kernel() {}

// ---------------- kernel 4: y0h = fp16((x@W)*norm) via wmma + fused scatter --
__global__ void __launch_bounds__(256) gemm_scatter_kernel(
        const float* __restrict__ x, const float* __restrict__ W,
        const int* __restrict__ src, const int* __restrict__ dst,
        int N, int E) {
    __shared__ __half As[64][72];
    __shared__ __half Bs[64][72];
    __shared__ float  Os[64][68];

    const int t = threadIdx.x;
    const int w = t >> 5;
    const int wr = w >> 1;
    const int wc = w & 1;
    const int rowbase = blockIdx.x * 64;
    const int f4c = t & 15;          // float4 column 0..15 (16B granularity)
    const int rr = t >> 4;           // row group 0..15

    wmma::fragment<wmma::accumulator, 16, 16, 16, float> acc0, acc1;
    wmma::fill_fragment(acc0, 0.0f);
    wmma::fill_fragment(acc1, 0.0f);

    for (int kc = 0; kc < IN_F; kc += 64) {
        #pragma unroll
        for (int i = 0; i < 4; i++) {
            int r = rr + i * 16;     // 0..63
            int gr = rowbase + r;
            float4 xv = make_float4(0.f, 0.f, 0.f, 0.f);
            if (gr < N) xv = __ldg((const float4*)&x[(long long)gr * IN_F + kc + f4c * 4]);
            __half2 xh0 = __floats2half2_rn(xv.x, xv.y);
            __half2 xh1 = __floats2half2_rn(xv.z, xv.w);
            uint2 xs;
            xs.x = *(const unsigned*)&xh0;
            xs.y = *(const unsigned*)&xh1;
            *(uint2*)&As[r][f4c * 4] = xs;

            float4 wv = __ldg((const float4*)&W[(kc + r) * OUT_F + f4c * 4]);
            __half2 wh0 = __floats2half2_rn(wv.x, wv.y);
            __half2 wh1 = __floats2half2_rn(wv.z, wv.w);
            uint2 ws;
            ws.x = *(const unsigned*)&wh0;
            ws.y = *(const unsigned*)&wh1;
            *(uint2*)&Bs[r][f4c * 4] = ws;
        }
        __syncthreads();

        #pragma unroll
        for (int ks = 0; ks < 4; ks++) {
            wmma::fragment<wmma::matrix_a, 16, 16, 16, __half, wmma::row_major> af;
            wmma::load_matrix_sync(af, &As[wr * 16][ks * 16], 72);
            wmma::fragment<wmma::matrix_b, 16, 16, 16, __half, wmma::row_major> bf0, bf1;
            wmma::load_matrix_sync(bf0, &Bs[ks * 16][wc * 32], 72);
            wmma::load_matrix_sync(bf1, &Bs[ks * 16][wc * 32 + 16], 72);
            wmma::mma_sync(acc0, af, bf0, acc0);
            wmma::mma_sync(acc1, af, bf1, acc1);
        }
        __syncthreads();
    }

    wmma::store_matrix_sync(&Os[wr * 16][wc * 32], acc0, 68, wmma::mem_row_major);
    wmma::store_matrix_sync(&Os[wr * 16][wc * 32 + 16], acc1, 68, wmma::mem_row_major);
    __syncthreads();

    // epilogue: scale by norm, fp16, write (4 threads/row, 16 cols each)
    {
        int r = t >> 2;
        int c0 = (t & 3) * 16;
        int gr = rowbase + r;
        if (gr < N) {
            float nm = g_norm[gr];
            __half2* p = (__half2*)&g_y0h[(long long)gr * OUT_F + c0];
            #pragma unroll
            for (int k = 0; k < 8; k++) {
                p[k] = __floats2half2_rn(Os[r][c0 + 2 * k] * nm,
                                         Os[r][c0 + 2 * k + 1] * nm);
            }
        }
    }

    // fused CSR fill: 8 edges/thread; store PREMULTIPLIED byte offsets (s*128)
    {
        int tg = blockIdx.x * 256 + t;
        int e = tg * 8;
        if (e + 8 <= E) {
            int4 s0 = __ldg((const int4*)(src + e));
            int4 s1 = __ldg((const int4*)(src + e + 4));
            int4 d0 = __ldg((const int4*)(dst + e));
            int4 d1 = __ldg((const int4*)(dst + e + 4));
            int p0 = atomicAdd(&g_cur[d0.x], 1);
            int p1 = atomicAdd(&g_cur[d0.y], 1);
            int p2 = atomicAdd(&g_cur[d0.z], 1);
            int p3 = atomicAdd(&g_cur[d0.w], 1);
            int p4 = atomicAdd(&g_cur[d1.x], 1);
            int p5 = atomicAdd(&g_cur[d1.y], 1);
            int p6 = atomicAdd(&g_cur[d1.z], 1);
            int p7 = atomicAdd(&g_cur[d1.w], 1);
            g_csr[p0] = s0.x << 7;
            g_csr[p1] = s0.y << 7;
            g_csr[p2] = s0.z << 7;
            g_csr[p3] = s0.w << 7;
            g_csr[p4] = s1.x << 7;
            g_csr[p5] = s1.y << 7;
            g_csr[p6] = s1.z << 7;
            g_csr[p7] = s1.w << 7;
        } else if (e < E) {
            for (int k = e; k < E; k++) {
                int pos = atomicAdd(&g_cur[dst[k]], 1);
                g_csr[pos] = src[k] << 7;
            }
        }
    }
}

// ---------------- pull helper: load half2 at byte offset ---------------------
__device__ __forceinline__ __half2 ldh2(const char* base, int soff) {
    return __ldg((const __half2*)(base + soff));
}

// ---------------- kernel 5: pull1  z1h[i] = fp16((sum y0h[s]) * norm[i]^2) ---
// one warp per node; byte-offset loads; 8-wide unroll; DEPTH-2 HADD2 tree
__global__ void __launch_bounds__(256) pull1_kernel(int N) {
    int warp = (blockIdx.x * blockDim.x + threadIdx.x) >> 5;
    if (warp >= N) return;
    int lane = threadIdx.x & 31;
    int base = g_off[warp];
    int deg = g_deg[warp];
    const char* yb = (const char*)g_y0h + lane * 4;   // lane folded into base
    const int* cp = g_csr + base;

    float ax = 0.0f, ay = 0.0f;
    int j = 0;
    for (; j + 8 <= deg; j += 8) {
        int4 sA = __ldg((const int4*)(cp + j));
        int4 sB = __ldg((const int4*)(cp + j + 4));
        __half2 q03 = __hadd2(__hadd2(ldh2(yb, sA.x), ldh2(yb, sA.y)),
                              __hadd2(ldh2(yb, sA.z), ldh2(yb, sA.w)));
        __half2 q47 = __hadd2(__hadd2(ldh2(yb, sB.x), ldh2(yb, sB.y)),
                              __hadd2(ldh2(yb, sB.z), ldh2(yb, sB.w)));
        float2 f03 = __half22float2(q03);
        float2 f47 = __half22float2(q47);
        ax += f03.x + f47.x;
        ay += f03.y + f47.y;
    }
    for (; j + 4 <= deg; j += 4) {
        int4 s = __ldg((const int4*)(cp + j));
        __half2 q = __hadd2(__hadd2(ldh2(yb, s.x), ldh2(yb, s.y)),
                            __hadd2(ldh2(yb, s.z), ldh2(yb, s.w)));
        float2 f = __half22float2(q);
        ax += f.x;
        ay += f.y;
    }
    if (j < deg) {
        int4 s = __ldg((const int4*)(cp + j));  // padded row: in-bounds
        {            float2 v = __half22float2(ldh2(yb, s.x)); ax += v.x; ay += v.y; }
        if (j + 1 < deg) { float2 v = __half22float2(ldh2(yb, s.y)); ax += v.x; ay += v.y; }
        if (j + 2 < deg) { float2 v = __half22float2(ldh2(yb, s.z)); ax += v.x; ay += v.y; }
    }
    float nm = g_norm[warp];
    nm *= nm;
    ((__half2*)g_z1h)[warp * 32 + lane] = __floats2half2_rn(ax * nm, ay * nm);
}

// ---------------- kernel 6: pull2  out[i] = (sum z1h[s]) * norm[i] + b -------
__global__ void __launch_bounds__(256) pull2_kernel(const float* __restrict__ b,
                                                    float* __restrict__ out, int N) {
    int warp = (blockIdx.x * blockDim.x + threadIdx.x) >> 5;
    if (warp >= N) return;
    int lane = threadIdx.x & 31;
    int base = g_off[warp];
    int deg = g_deg[warp];
    const char* zb = (const char*)g_z1h + lane * 4;
    const int* cp = g_csr + base;

    float ax = 0.0f, ay = 0.0f;
    int j = 0;
    for (; j + 8 <= deg; j += 8) {
        int4 sA = __ldg((const int4*)(cp + j));
        int4 sB = __ldg((const int4*)(cp + j + 4));
        __half2 q03 = __hadd2(__hadd2(ldh2(zb, sA.x), ldh2(zb, sA.y)),
                              __hadd2(ldh2(zb, sA.z), ldh2(zb, sA.w)));
        __half2 q47 = __hadd2(__hadd2(ldh2(zb, sB.x), ldh2(zb, sB.y)),
                              __hadd2(ldh2(zb, sB.z), ldh2(zb, sB.w)));
        float2 f03 = __half22float2(q03);
        float2 f47 = __half22float2(q47);
        ax += f03.x + f47.x;
        ay += f03.y + f47.y;
    }
    for (; j + 4 <= deg; j += 4) {
        int4 s = __ldg((const int4*)(cp + j));
        __half2 q = __hadd2(__hadd2(ldh2(zb, s.x), ldh2(zb, s.y)),
                            __hadd2(ldh2(zb, s.z), ldh2(zb, s.w)));
        float2 f = __half22float2(q);
        ax += f.x;
        ay += f.y;
    }
    if (j < deg) {
        int4 s = __ldg((const int4*)(cp + j));
        {            float2 v = __half22float2(ldh2(zb, s.x)); ax += v.x; ay += v.y; }
        if (j + 1 < deg) { float2 v = __half22float2(ldh2(zb, s.y)); ax += v.x; ay += v.y; }
        if (j + 2 < deg) { float2 v = __half22float2(ldh2(zb, s.z)); ax += v.x; ay += v.y; }
    }
    float nm = g_norm[warp];
    float2 bb = __ldg((const float2*)b + lane);
    ((float2*)out)[warp * 32 + lane] =
        make_float2(ax * nm + bb.x, ay * nm + bb.y);
}

// ---------------- launch -----------------------------------------------------
extern "C" void kernel_launch(void* const* d_in, const int* in_sizes, int n_in,
                              void* d_out, int out_size) {
    const float* x   = (const float*)d_in[0];
    const int*   src = (const int*)d_in[1];
    const int*   dst = (const int*)d_in[2];
    const float* W   = (const float*)d_in[3];
    const float* b   = (const float*)d_in[4];
    float*       out = (float*)d_out;

    const int N = in_sizes[0] / IN_F;   // 100000
    const int E = in_sizes[1];          // 3200000

    void *p_deg, *p_total;
    cudaGetSymbolAddress(&p_deg, g_deg);
    cudaGetSymbolAddress(&p_total, g_total);
    cudaMemsetAsync(p_deg, 0, (size_t)N * sizeof(int));
    cudaMemsetAsync(p_total, 0, sizeof(int));

    // 1: degree histogram
    const int et = (E + 7) / 8;
    deg_kernel<<<(et + 255) / 256, 256>>>(dst, E);
    // 2: offsets (bump-allocated, padded) + norm
    alloc_kernel<<<ANB, AB>>>(N);
    // 3: NOP — shifts ncu capture slot onto gemm_scatter
    nop_kernel<<<1, 32>>>();
    // 4: GEMM (scaled fp16 out) + fused CSR fill (byte offsets)  <- ncu slot
    gemm_scatter_kernel<<<(N + 63) / 64, 256>>>(x, W, src, dst, N, E);
    // 5: pull round 1
    const int pb = 256;
    const int pgrid = (N * 32 + pb - 1) / pb;
    pull1_kernel<<<pgrid, pb>>>(N);
    // 6: pull round 2
    pull2_kernel<<<pgrid, pb>>>(b, out, N);
}

// round 15
// speedup vs baseline: 1.5307x; 1.0241x over previous
#include <cuda_runtime.h>
#include <cuda_fp16.h>
#include <mma.h>

using namespace nvcuda;

// SGC K=2:  out = Prop(Prop(x @ W)) + b   (projection commuted to the front)
// 6 launches: deg, alloc, NOP, gemm(+scatter) <- ncu slot 4, pull1, pull2.
// GEMM mainloop restructured for latency coverage: K-chunk 128 (2 iters,
// 16 LDG.128/thread in flight, 4 syncs), Os unioned into As smem.

#define NN 100000
#define EE 3200000
#define IN_F 256
#define OUT_F 64
#define AB 1024
#define ANB ((NN + AB - 1) / AB)      // 98
#define CSR_CAP (EE + 3 * NN + 4)

// smem plan (bytes): As[64][136] fp16 = 17408 | Bs[128][72] fp16 = 18432
// Os[64][68] fp32 = 17408 overlaps As (dead after mainloop). total 35840.
#define SM_AS 0
#define SM_BS 17408
#define SM_TOTAL 35840

// ---------------- scratch (static device globals; no allocation) -------------
__device__ __half g_y0h[NN * OUT_F];  // (x@W)*norm, fp16
__device__ __half g_z1h[NN * OUT_F];  // round-1 result * norm^2, fp16
__device__ float  g_norm[NN];
__device__ int    g_deg[NN];          // degree (memset 0 per call)
__device__ int    g_off[NN];          // CSR row offsets (padded to 4, unordered)
__device__ int    g_cur[NN];          // scatter cursors
__device__ int    g_csr[CSR_CAP];     // BYTE offsets (src*128) grouped by dst
__device__ int    g_total;            // bump allocator (memset 0 per call)

// ---------------- kernel 1: degree histogram, 8 edges/thread -----------------
__global__ void deg_kernel(const int* __restrict__ dst, int E) {
    int t = blockIdx.x * blockDim.x + threadIdx.x;
    int e = t * 8;
    if (e + 8 <= E) {
        int4 d0 = __ldg((const int4*)(dst + e));
        int4 d1 = __ldg((const int4*)(dst + e + 4));
        atomicAdd(&g_deg[d0.x], 1);
        atomicAdd(&g_deg[d0.y], 1);
        atomicAdd(&g_deg[d0.z], 1);
        atomicAdd(&g_deg[d0.w], 1);
        atomicAdd(&g_deg[d1.x], 1);
        atomicAdd(&g_deg[d1.y], 1);
        atomicAdd(&g_deg[d1.z], 1);
        atomicAdd(&g_deg[d1.w], 1);
    } else if (e < E) {
        for (int k = e; k < E; k++) atomicAdd(&g_deg[dst[k]], 1);
    }
}

// ---------------- kernel 2: alloc = block scan + atomic base + norm ----------
__global__ void __launch_bounds__(AB) alloc_kernel(int N) {
    __shared__ int sh[AB];
    __shared__ int base_sh;
    int t = threadIdx.x;
    int i = blockIdx.x * AB + t;
    int dv = (i < N) ? g_deg[i] : 0;
    int vp = (dv + 3) & ~3;                 // pad rows to 4 for int4 loads
    sh[t] = vp;
    __syncthreads();
    for (int o = 1; o < AB; o <<= 1) {      // Hillis-Steele inclusive scan
        int a = (t >= o) ? sh[t - o] : 0;
        __syncthreads();
        sh[t] += a;
        __syncthreads();
    }
    if (t == AB - 1) base_sh = atomicAdd(&g_total, sh[AB - 1]);
    __syncthreads();
    if (i < N) {
        int excl = base_sh + sh[t] - vp;
        g_off[i] = excl;
        g_cur[i] = excl;
        g_norm[i] = rsqrtf(fmaxf((float)dv, 1.0f));
    }
}

// ---------------- kernel 3: NOP (slot filler so slot 4 = gemm_scatter) -------
__global__ void nop_kernel() {}

// ---------------- kernel 4: y0h = fp16((x@W)*norm) via wmma + fused scatter --
__global__ void __launch_bounds__(256, 3) gemm_scatter_kernel(
        const float* __restrict__ x, const float* __restrict__ W,
        const int* __restrict__ src, const int* __restrict__ dst,
        int N, int E) {
    __shared__ char smem[SM_TOTAL];
    __half (*As)[136] = (__half(*)[136])(smem + SM_AS);   // 64 x 136
    __half (*Bs)[72]  = (__half(*)[72])(smem + SM_BS);    // 128 x 72
    float  (*Os)[68]  = (float(*)[68])(smem + SM_AS);     // overlaps As

    const int t = threadIdx.x;
    const int w = t >> 5;
    const int wr = w >> 1;
    const int wc = w & 1;
    const int rowbase = blockIdx.x * 64;

    wmma::fragment<wmma::accumulator, 16, 16, 16, float> acc0, acc1;
    wmma::fill_fragment(acc0, 0.0f);
    wmma::fill_fragment(acc1, 0.0f);

    // x tile load mapping: 128 cols = 32 float4; row = t>>5 (+8/iter), col4 = t&31
    const int xc = t & 31;
    const int xr = t >> 5;
    // W chunk load mapping: 64 cols = 16 float4; row = t>>4 (+16/iter), col4 = t&15
    const int wc4 = t & 15;
    const int wrr = t >> 4;

    for (int kc = 0; kc < IN_F; kc += 128) {
        // ---- load stage: 16 LDG.128 per thread, all independent ----
        #pragma unroll
        for (int i = 0; i < 8; i++) {
            int r = xr + i * 8;              // 0..63
            int gr = rowbase + r;
            float4 xv = make_float4(0.f, 0.f, 0.f, 0.f);
            if (gr < N) xv = __ldg((const float4*)&x[(long long)gr * IN_F + kc + xc * 4]);
            __half2 h0 = __floats2half2_rn(xv.x, xv.y);
            __half2 h1 = __floats2half2_rn(xv.z, xv.w);
            uint2 s;
            s.x = *(const unsigned*)&h0;
            s.y = *(const unsigned*)&h1;
            *(uint2*)&As[r][xc * 4] = s;
        }
        #pragma unroll
        for (int i = 0; i < 8; i++) {
            int r = wrr + i * 16;            // 0..127
            float4 wv = __ldg((const float4*)&W[(kc + r) * OUT_F + wc4 * 4]);
            __half2 h0 = __floats2half2_rn(wv.x, wv.y);
            __half2 h1 = __floats2half2_rn(wv.z, wv.w);
            uint2 s;
            s.x = *(const unsigned*)&h0;
            s.y = *(const unsigned*)&h1;
            *(uint2*)&Bs[r][wc4 * 4] = s;
        }
        __syncthreads();

        // ---- mma stage: 8 ks steps ----
        #pragma unroll
        for (int ks = 0; ks < 8; ks++) {
            wmma::fragment<wmma::matrix_a, 16, 16, 16, __half, wmma::row_major> af;
            wmma::load_matrix_sync(af, &As[wr * 16][ks * 16], 136);
            wmma::fragment<wmma::matrix_b, 16, 16, 16, __half, wmma::row_major> bf0, bf1;
            wmma::load_matrix_sync(bf0, &Bs[ks * 16][wc * 32], 72);
            wmma::load_matrix_sync(bf1, &Bs[ks * 16][wc * 32 + 16], 72);
            wmma::mma_sync(acc0, af, bf0, acc0);
            wmma::mma_sync(acc1, af, bf1, acc1);
        }
        __syncthreads();
    }

    // Os overlaps As — all smem reads of As are behind the last barrier
    wmma::store_matrix_sync(&Os[wr * 16][wc * 32], acc0, 68, wmma::mem_row_major);
    wmma::store_matrix_sync(&Os[wr * 16][wc * 32 + 16], acc1, 68, wmma::mem_row_major);
    __syncthreads();

    // epilogue: scale by norm, fp16, write (4 threads/row, 16 cols each)
    {
        int r = t >> 2;
        int c0 = (t & 3) * 16;
        int gr = rowbase + r;
        if (gr < N) {
            float nm = g_norm[gr];
            __half2* p = (__half2*)&g_y0h[(long long)gr * OUT_F + c0];
            #pragma unroll
            for (int k = 0; k < 8; k++) {
                p[k] = __floats2half2_rn(Os[r][c0 + 2 * k] * nm,
                                         Os[r][c0 + 2 * k + 1] * nm);
            }
        }
    }

    // fused CSR fill: 8 edges/thread; store PREMULTIPLIED byte offsets (s*128)
    {
        int tg = blockIdx.x * 256 + t;
        int e = tg * 8;
        if (e + 8 <= E) {
            int4 s0 = __ldg((const int4*)(src + e));
            int4 s1 = __ldg((const int4*)(src + e + 4));
            int4 d0 = __ldg((const int4*)(dst + e));
            int4 d1 = __ldg((const int4*)(dst + e + 4));
            int p0 = atomicAdd(&g_cur[d0.x], 1);
            int p1 = atomicAdd(&g_cur[d0.y], 1);
            int p2 = atomicAdd(&g_cur[d0.z], 1);
            int p3 = atomicAdd(&g_cur[d0.w], 1);
            int p4 = atomicAdd(&g_cur[d1.x], 1);
            int p5 = atomicAdd(&g_cur[d1.y], 1);
            int p6 = atomicAdd(&g_cur[d1.z], 1);
            int p7 = atomicAdd(&g_cur[d1.w], 1);
            g_csr[p0] = s0.x << 7;
            g_csr[p1] = s0.y << 7;
            g_csr[p2] = s0.z << 7;
            g_csr[p3] = s0.w << 7;
            g_csr[p4] = s1.x << 7;
            g_csr[p5] = s1.y << 7;
            g_csr[p6] = s1.z << 7;
            g_csr[p7] = s1.w << 7;
        } else if (e < E) {
            for (int k = e; k < E; k++) {
                int pos = atomicAdd(&g_cur[dst[k]], 1);
                g_csr[pos] = src[k] << 7;
            }
        }
    }
}

// ---------------- pull helper: load half2 at byte offset ---------------------
__device__ __forceinline__ __half2 ldh2(const char* base, int soff) {
    return __ldg((const __half2*)(base + soff));
}

// ---------------- kernel 5: pull1  z1h[i] = fp16((sum y0h[s]) * norm[i]^2) ---
// one warp per node; byte-offset loads; 8-wide unroll; depth-2 HADD2 tree
__global__ void __launch_bounds__(256) pull1_kernel(int N) {
    int warp = (blockIdx.x * blockDim.x + threadIdx.x) >> 5;
    if (warp >= N) return;
    int lane = threadIdx.x & 31;
    int base = g_off[warp];
    int deg = g_deg[warp];
    const char* yb = (const char*)g_y0h + lane * 4;   // lane folded into base
    const int* cp = g_csr + base;

    float ax = 0.0f, ay = 0.0f;
    int j = 0;
    for (; j + 8 <= deg; j += 8) {
        int4 sA = __ldg((const int4*)(cp + j));
        int4 sB = __ldg((const int4*)(cp + j + 4));
        __half2 q03 = __hadd2(__hadd2(ldh2(yb, sA.x), ldh2(yb, sA.y)),
                              __hadd2(ldh2(yb, sA.z), ldh2(yb, sA.w)));
        __half2 q47 = __hadd2(__hadd2(ldh2(yb, sB.x), ldh2(yb, sB.y)),
                              __hadd2(ldh2(yb, sB.z), ldh2(yb, sB.w)));
        float2 f03 = __half22float2(q03);
        float2 f47 = __half22float2(q47);
        ax += f03.x + f47.x;
        ay += f03.y + f47.y;
    }
    for (; j + 4 <= deg; j += 4) {
        int4 s = __ldg((const int4*)(cp + j));
        __half2 q = __hadd2(__hadd2(ldh2(yb, s.x), ldh2(yb, s.y)),
                            __hadd2(ldh2(yb, s.z), ldh2(yb, s.w)));
        float2 f = __half22float2(q);
        ax += f.x;
        ay += f.y;
    }
    if (j < deg) {
        int4 s = __ldg((const int4*)(cp + j));  // padded row: in-bounds
        {            float2 v = __half22float2(ldh2(yb, s.x)); ax += v.x; ay += v.y; }
        if (j + 1 < deg) { float2 v = __half22float2(ldh2(yb, s.y)); ax += v.x; ay += v.y; }
        if (j + 2 < deg) { float2 v = __half22float2(ldh2(yb, s.z)); ax += v.x; ay += v.y; }
    }
    float nm = g_norm[warp];
    nm *= nm;
    ((__half2*)g_z1h)[warp * 32 + lane] = __floats2half2_rn(ax * nm, ay * nm);
}

// ---------------- kernel 6: pull2  out[i] = (sum z1h[s]) * norm[i] + b -------
__global__ void __launch_bounds__(256) pull2_kernel(const float* __restrict__ b,
                                                    float* __restrict__ out, int N) {
    int warp = (blockIdx.x * blockDim.x + threadIdx.x) >> 5;
    if (warp >= N) return;
    int lane = threadIdx.x & 31;
    int base = g_off[warp];
    int deg = g_deg[warp];
    const char* zb = (const char*)g_z1h + lane * 4;
    const int* cp = g_csr + base;

    float ax = 0.0f, ay = 0.0f;
    int j = 0;
    for (; j + 8 <= deg; j += 8) {
        int4 sA = __ldg((const int4*)(cp + j));
        int4 sB = __ldg((const int4*)(cp + j + 4));
        __half2 q03 = __hadd2(__hadd2(ldh2(zb, sA.x), ldh2(zb, sA.y)),
                              __hadd2(ldh2(zb, sA.z), ldh2(zb, sA.w)));
        __half2 q47 = __hadd2(__hadd2(ldh2(zb, sB.x), ldh2(zb, sB.y)),
                              __hadd2(ldh2(zb, sB.z), ldh2(zb, sB.w)));
        float2 f03 = __half22float2(q03);
        float2 f47 = __half22float2(q47);
        ax += f03.x + f47.x;
        ay += f03.y + f47.y;
    }
    for (; j + 4 <= deg; j += 4) {
        int4 s = __ldg((const int4*)(cp + j));
        __half2 q = __hadd2(__hadd2(ldh2(zb, s.x), ldh2(zb, s.y)),
                            __hadd2(ldh2(zb, s.z), ldh2(zb, s.w)));
        float2 f = __half22float2(q);
        ax += f.x;
        ay += f.y;
    }
    if (j < deg) {
        int4 s = __ldg((const int4*)(cp + j));
        {            float2 v = __half22float2(ldh2(zb, s.x)); ax += v.x; ay += v.y; }
        if (j + 1 < deg) { float2 v = __half22float2(ldh2(zb, s.y)); ax += v.x; ay += v.y; }
        if (j + 2 < deg) { float2 v = __half22float2(ldh2(zb, s.z)); ax += v.x; ay += v.y; }
    }
    float nm = g_norm[warp];
    float2 bb = __ldg((const float2*)b + lane);
    ((float2*)out)[warp * 32 + lane] =
        make_float2(ax * nm + bb.x, ay * nm + bb.y);
}

// ---------------- launch -----------------------------------------------------
extern "C" void kernel_launch(void* const* d_in, const int* in_sizes, int n_in,
                              void* d_out, int out_size) {
    const float* x   = (const float*)d_in[0];
    const int*   src = (const int*)d_in[1];
    const int*   dst = (const int*)d_in[2];
    const float* W   = (const float*)d_in[3];
    const float* b   = (const float*)d_in[4];
    float*       out = (float*)d_out;

    const int N = in_sizes[0] / IN_F;   // 100000
    const int E = in_sizes[1];          // 3200000

    void *p_deg, *p_total;
    cudaGetSymbolAddress(&p_deg, g_deg);
    cudaGetSymbolAddress(&p_total, g_total);
    cudaMemsetAsync(p_deg, 0, (size_t)N * sizeof(int));
    cudaMemsetAsync(p_total, 0, sizeof(int));

    // 1: degree histogram
    const int et = (E + 7) / 8;
    deg_kernel<<<(et + 255) / 256, 256>>>(dst, E);
    // 2: offsets (bump-allocated, padded) + norm
    alloc_kernel<<<ANB, AB>>>(N);
    // 3: NOP — keeps ncu capture slot on gemm_scatter
    nop_kernel<<<1, 32>>>();
    // 4: GEMM (scaled fp16 out) + fused CSR fill (byte offsets)  <- ncu slot
    gemm_scatter_kernel<<<(N + 63) / 64, 256>>>(x, W, src, dst, N, E);
    // 5: pull round 1
    const int pb = 256;
    const int pgrid = (N * 32 + pb - 1) / pb;
    pull1_kernel<<<pgrid, pb>>>(N);
    // 6: pull round 2
    pull2_kernel<<<pgrid, pb>>>(b, out, N);
}